// round 3
// baseline (speedup 1.0000x reference)
#include <cuda_runtime.h>

#define Bb 4
#define Ss 1024
#define Dd 32
#define Hh 32
#define NBLK (Bb * Hh)   // 128 blocks, all resident in wave 1

// scratch: c[b,h] = sum_j softmax_j(K[b,:,h]) * V[b,j,h]
__device__ float g_c[Bb * Hh];
__device__ unsigned g_cnt;   // monotonic epoch counter (zero-init; +128 per call)

__global__ void __launch_bounds__(256, 1) foaa_fused(
    const float* __restrict__ x,
    const float* __restrict__ Wk, const float* __restrict__ bk,
    const float* __restrict__ Wv, const float* __restrict__ bv,
    const float* __restrict__ Wo, const float* __restrict__ bo,
    float* __restrict__ out)
{
    const int b = blockIdx.x >> 5;   // blockIdx.x = b*32 + h
    const int h = blockIdx.x & 31;
    const int tid = threadIdx.x;

    __shared__ float wk[Dd], wv[Dd];
    __shared__ float s_Wo[Dd * Dd];
    __shared__ float s_bo[Dd];
    __shared__ __align__(16) float y[Dd];
    __shared__ float sm[8], ss[8], ssv[8];

    // Prefetch stage-2 weights NOW so their DRAM latency overlaps stage 1.
    for (int i = tid; i < Dd * Dd; i += 256) s_Wo[i] = Wo[i];
    if (tid < Dd) s_bo[tid] = bo[tid];

    if (tid < Dd)            wk[tid]      = Wk[h * Dd + tid];
    else if (tid < 2 * Dd)   wv[tid - Dd] = Wv[h * Dd + (tid - Dd)];
    __syncthreads();

    const float bkh = bk[h];
    const float bvh = bv[h];

    // ---- Stage 1: online softmax-weighted reduction over j for (b,h) ----
    float m = -1e30f, s = 0.0f, sv = 0.0f;
    const float* xb = x + (size_t)b * Ss * Dd;

    for (int j = tid; j < Ss; j += 256) {
        const float4* row = (const float4*)(xb + j * Dd);
        float k = bkh, v = bvh;
        #pragma unroll
        for (int q = 0; q < 8; q++) {
            float4 xv = row[q];
            k = fmaf(xv.x, wk[4*q+0], k); k = fmaf(xv.y, wk[4*q+1], k);
            k = fmaf(xv.z, wk[4*q+2], k); k = fmaf(xv.w, wk[4*q+3], k);
            v = fmaf(xv.x, wv[4*q+0], v); v = fmaf(xv.y, wv[4*q+1], v);
            v = fmaf(xv.z, wv[4*q+2], v); v = fmaf(xv.w, wv[4*q+3], v);
        }
        float mn = fmaxf(m, k);
        float scale = __expf(m - mn);
        float e     = __expf(k - mn);
        s  = s * scale + e;
        sv = sv * scale + e * v;
        m = mn;
    }

    #pragma unroll
    for (int off = 16; off; off >>= 1) {
        float m2  = __shfl_xor_sync(0xffffffffu, m,  off);
        float s2  = __shfl_xor_sync(0xffffffffu, s,  off);
        float sv2 = __shfl_xor_sync(0xffffffffu, sv, off);
        float mn = fmaxf(m, m2);
        float a  = __expf(m  - mn);
        float c2 = __expf(m2 - mn);
        s  = s  * a + s2  * c2;
        sv = sv * a + sv2 * c2;
        m = mn;
    }

    const int w = tid >> 5, lane = tid & 31;
    if (lane == 0) { sm[w] = m; ss[w] = s; ssv[w] = sv; }
    __syncthreads();

    // ---- Publish c[b,h], then grid barrier (epoch-based, graph-safe) ----
    if (tid == 0) {
        m = sm[0]; s = ss[0]; sv = ssv[0];
        #pragma unroll
        for (int i = 1; i < 8; i++) {
            float mn = fmaxf(m, sm[i]);
            float a  = __expf(m     - mn);
            float c2 = __expf(sm[i] - mn);
            s  = s  * a + ss[i]  * c2;
            sv = sv * a + ssv[i] * c2;
            m = mn;
        }
        g_c[b * Hh + h] = sv / s;
        __threadfence();
        unsigned c0 = atomicAdd(&g_cnt, 1u);
        unsigned target = ((c0 >> 7) + 1u) << 7;   // next multiple of 128
        unsigned vcur;
        do {
            asm volatile("ld.acquire.gpu.u32 %0, [%1];"
                         : "=r"(vcur) : "l"(&g_cnt));
        } while (vcur < target);
    }
    __syncthreads();

    // ---- Stage 2: y[b2,d] = bo[d] + sum_h c[b2,h]*Wo[d,h]; each block
    //      writes 32 rows (4 KB) of the broadcast output ----
    const int b2 = blockIdx.x >> 5;              // 32 blocks per batch
    if (tid < Dd) {
        float acc = s_bo[tid];
        #pragma unroll
        for (int hh = 0; hh < Hh; hh++)
            acc = fmaf(g_c[b2 * Hh + hh], s_Wo[tid * Dd + hh], acc);
        y[tid] = acc;
    }
    __syncthreads();

    float4* outp = (float4*)(out + (size_t)blockIdx.x * 32 * Dd);
    float4 v4 = *(const float4*)&y[(tid * 4) & (Dd - 1)];
    outp[tid] = v4;
}

extern "C" void kernel_launch(void* const* d_in, const int* in_sizes, int n_in,
                              void* d_out, int out_size)
{
    // metadata order: x, Wq, bq, Wk, bk, Wv, bv, Wo, bo
    const float* x  = (const float*)d_in[0];
    const float* Wk = (const float*)d_in[3];
    const float* bk = (const float*)d_in[4];
    const float* Wv = (const float*)d_in[5];
    const float* bv = (const float*)d_in[6];
    const float* Wo = (const float*)d_in[7];
    const float* bo = (const float*)d_in[8];
    float* out = (float*)d_out;

    foaa_fused<<<NBLK, 256>>>(x, Wk, bk, Wv, bv, Wo, bo, out);
}

// round 4
// speedup vs baseline: 1.4669x; 1.4669x over previous
#include <cuda_runtime.h>

#define Bb 4
#define Ss 1024
#define Dd 32
#define Hh 32
#define NBLK (Bb * Hh)     // 128 blocks, all resident in wave 1
#define NTHR 512           // 16 warps

// scratch: c[b,h] = sum_j softmax_j(K[b,:,h]) * V[b,j,h]
__device__ float g_c[Bb * Hh];
__device__ unsigned g_cnt;   // monotonic epoch counter (zero-init; +128/call)

__global__ void __launch_bounds__(NTHR, 1) foaa_fused(
    const float* __restrict__ x,
    const float* __restrict__ Wk, const float* __restrict__ bk,
    const float* __restrict__ Wv, const float* __restrict__ bv,
    const float* __restrict__ Wo, const float* __restrict__ bo,
    float* __restrict__ out)
{
    const int b = blockIdx.x >> 5;     // blockIdx.x = b*32 + h
    const int h = blockIdx.x & 31;
    const int tid  = threadIdx.x;
    const int w    = tid >> 5;         // warp 0..15
    const int lane = tid & 31;
    const int e8   = lane & 7;         // column-quarter within row

    __shared__ float s_Wo[Dd * Dd];
    __shared__ float s_bo[Dd];
    __shared__ __align__(16) float y[Dd];
    __shared__ float ss[16], ssv[16];

    // Prefetch stage-2 weights NOW; DRAM latency overlaps stage 1.
    for (int i = tid; i < Dd * Dd; i += NTHR) s_Wo[i] = Wo[i];
    if (tid < Dd) s_bo[tid] = bo[tid];

    // Per-lane weight slice (4 columns). bk cancels in softmax; bv added at end.
    const float4 wk4 = ((const float4*)(Wk + h * Dd))[e8];
    const float4 wv4 = ((const float4*)(Wv + h * Dd))[e8];
    const float  bvh = bv[h];

    // ---- Stage 1: sum_j exp(k_j) and sum_j exp(k_j)*v_j for (b,h) ----
    // Quarter-warp layout: lanes 8g..8g+7 process row (quad*4+g); a warp's
    // LDG covers 512 contiguous bytes (4 rows) -> fully coalesced.
    const float4* xq = (const float4*)(x + (size_t)b * Ss * Dd);

    float s = 0.0f, sv = 0.0f;
    #pragma unroll
    for (int it = 0; it < Ss / 4 / 16; it++) {      // 16 iterations
        const int quad = it * 16 + w;               // 4-row group index
        float4 xv = xq[quad * 32 + lane];

        float kp = xv.x * wk4.x + xv.y * wk4.y + xv.z * wk4.z + xv.w * wk4.w;
        float vp = xv.x * wv4.x + xv.y * wv4.y + xv.z * wv4.z + xv.w * wv4.w;

        // reduce over the 8 lanes of this row
        #pragma unroll
        for (int off = 1; off < 8; off <<= 1) {
            kp += __shfl_xor_sync(0xffffffffu, kp, off);
            vp += __shfl_xor_sync(0xffffffffu, vp, off);
        }
        float e = __expf(kp);
        s  += e;
        sv = fmaf(e, vp, sv);
    }
    // merge the 4 row-subgroups of the warp (values identical within subgroup)
    #pragma unroll
    for (int off = 8; off < 32; off <<= 1) {
        s  += __shfl_xor_sync(0xffffffffu, s,  off);
        sv += __shfl_xor_sync(0xffffffffu, sv, off);
    }
    if (lane == 0) { ss[w] = s; ssv[w] = sv; }
    __syncthreads();

    // ---- Publish c[b,h], then grid barrier (epoch-based, graph-safe) ----
    if (tid == 0) {
        float S = 0.0f, SV = 0.0f;
        #pragma unroll
        for (int i = 0; i < 16; i++) { S += ss[i]; SV += ssv[i]; }
        g_c[b * Hh + h] = SV / S + bvh;
        __threadfence();
        unsigned c0 = atomicAdd(&g_cnt, 1u);
        unsigned target = ((c0 >> 7) + 1u) << 7;   // next multiple of 128
        unsigned vcur;
        do {
            asm volatile("ld.acquire.gpu.u32 %0, [%1];"
                         : "=r"(vcur) : "l"(&g_cnt));
        } while (vcur < target);
    }
    __syncthreads();

    // ---- Stage 2: y[b,d] = bo[d] + sum_h c[b,h]*Wo[d,h]; each block
    //      writes 32 rows (4 KB) of the broadcast output ----
    if (tid < Dd) {
        float acc = s_bo[tid];
        #pragma unroll
        for (int hh = 0; hh < Hh; hh++)
            acc = fmaf(g_c[b * Hh + hh], s_Wo[tid * Dd + hh], acc);
        y[tid] = acc;
    }
    __syncthreads();

    if (tid < 256) {
        float4* outp = (float4*)(out + (size_t)blockIdx.x * 32 * Dd);
        outp[tid] = ((const float4*)y)[tid & 7];
    }
}

extern "C" void kernel_launch(void* const* d_in, const int* in_sizes, int n_in,
                              void* d_out, int out_size)
{
    // metadata order: x, Wq, bq, Wk, bk, Wv, bv, Wo, bo
    const float* x  = (const float*)d_in[0];
    const float* Wk = (const float*)d_in[3];
    const float* bk = (const float*)d_in[4];
    const float* Wv = (const float*)d_in[5];
    const float* bv = (const float*)d_in[6];
    const float* Wo = (const float*)d_in[7];
    const float* bo = (const float*)d_in[8];
    float* out = (float*)d_out;

    foaa_fused<<<NBLK, NTHR>>>(x, Wk, bk, Wv, bv, Wo, bo, out);
}